// round 2
// baseline (speedup 1.0000x reference)
#include <cuda_runtime.h>
#include <math.h>

// Problem dims
#define BB   2
#define LTT  2048
#define LSS  2048
#define DD   1024
#define HH   16
#define DKK  64
#define DFFF 4096
#define MR   (BB*LTT)   // 4096 rows

// ---------------- scratch (__device__ globals, no allocs) ----------------
__device__ float g_q   [(size_t)MR*DD];
__device__ float g_k   [(size_t)MR*DD];
__device__ float g_v   [(size_t)MR*DD];
__device__ float g_attn[(size_t)MR*DD];
__device__ float g_tmp [(size_t)MR*DD];
__device__ float g_x1  [(size_t)MR*DD];
__device__ float g_x2  [(size_t)MR*DD];
__device__ float g_ff  [(size_t)MR*DFFF];
__device__ float g_sc  [(size_t)BB*HH*LTT*LSS];   // 536 MB score/prob matrix

// ---------------- generic SGEMM: C = A[M,K] @ W[K,N] + bias (+gelu) -------
// BM=BN=128, BK=8, 256 threads, 8x8 per thread. All dims divisible.
__global__ void __launch_bounds__(256) sgemm(
    const float* __restrict__ A, const float* __restrict__ W,
    const float* __restrict__ bias, float* __restrict__ C,
    int M, int N, int K, int act)
{
    __shared__ float As[8][128];
    __shared__ float Ws[8][128];
    const int tid  = threadIdx.x;
    const int brow = blockIdx.y << 7;
    const int bcol = blockIdx.x << 7;
    const int arow = tid >> 1;
    const int acol = (tid & 1) << 2;
    const int wrow = tid >> 5;
    const int wcol = (tid & 31) << 2;
    const int ty   = (tid >> 4) << 3;
    const int tx   = (tid & 15) << 3;

    float acc[8][8];
    #pragma unroll
    for (int i = 0; i < 8; i++)
        #pragma unroll
        for (int j = 0; j < 8; j++) acc[i][j] = 0.f;

    const float* Ap = A + (size_t)(brow + arow) * K + acol;
    const float* Wp = W + (size_t)wrow * N + bcol + wcol;

    for (int k0 = 0; k0 < K; k0 += 8) {
        float4 av = *(const float4*)(Ap + k0);
        As[acol + 0][arow] = av.x;
        As[acol + 1][arow] = av.y;
        As[acol + 2][arow] = av.z;
        As[acol + 3][arow] = av.w;
        float4 wv = *(const float4*)(Wp + (size_t)k0 * N);
        *(float4*)&Ws[wrow][wcol] = wv;
        __syncthreads();
        #pragma unroll
        for (int k = 0; k < 8; k++) {
            float a_[8], b_[8];
            #pragma unroll
            for (int i = 0; i < 8; i++) a_[i] = As[k][ty + i];
            #pragma unroll
            for (int j = 0; j < 8; j++) b_[j] = Ws[k][tx + j];
            #pragma unroll
            for (int i = 0; i < 8; i++)
                #pragma unroll
                for (int j = 0; j < 8; j++)
                    acc[i][j] = fmaf(a_[i], b_[j], acc[i][j]);
        }
        __syncthreads();
    }
    #pragma unroll
    for (int i = 0; i < 8; i++) {
        size_t r = (size_t)(brow + ty + i);
        #pragma unroll
        for (int j = 0; j < 8; j++) {
            int c = bcol + tx + j;
            float v = acc[i][j] + bias[c];
            if (act == 1) v = 0.5f * v * (1.f + erff(v * 0.70710678118654752f));
            C[r * N + c] = v;
        }
    }
}

// -------- batched attention scores: S[bh,i,j] = scale * Q_h[i].K_h[j], masked
// mode 0: tgt_mask[LT,LT] (causal tril) ; mode 1: src_mask[B,1,1,LS]
__global__ void __launch_bounds__(256) attn_scores(
    const float* __restrict__ Q, const float* __restrict__ Kmat,
    const int* __restrict__ mask, float* __restrict__ S,
    int Lq, int Lk, int mode, float scale)
{
    const int bh = blockIdx.z;
    const int b  = bh / HH;
    const int h  = bh % HH;
    const int i0 = blockIdx.y << 6;
    const int j0 = blockIdx.x << 6;
    const int tid = threadIdx.x;
    const int ty  = (tid >> 4) << 2;
    const int tx  = (tid & 15) << 2;
    float* Sp = S + (size_t)bh * Lq * Lk;

    if (mode == 0 && j0 > i0 + 63) {   // fully masked causal tile
        #pragma unroll
        for (int ii = 0; ii < 4; ii++)
            #pragma unroll
            for (int jj = 0; jj < 4; jj++)
                Sp[(size_t)(i0 + ty + ii) * Lk + j0 + tx + jj] = -1e9f;
        return;
    }

    __shared__ float Qs[64][65];   // [k][i]
    __shared__ float Ks[64][65];   // [k][j]
    const int lrow = tid >> 4;
    const int lcol = (tid & 15) << 2;
    #pragma unroll
    for (int r = 0; r < 4; r++) {
        int row = lrow + (r << 4);
        float4 qv = *(const float4*)(Q + (size_t)(b * Lq + i0 + row) * DD + h * DKK + lcol);
        Qs[lcol + 0][row] = qv.x; Qs[lcol + 1][row] = qv.y;
        Qs[lcol + 2][row] = qv.z; Qs[lcol + 3][row] = qv.w;
        float4 kv = *(const float4*)(Kmat + (size_t)(b * Lk + j0 + row) * DD + h * DKK + lcol);
        Ks[lcol + 0][row] = kv.x; Ks[lcol + 1][row] = kv.y;
        Ks[lcol + 2][row] = kv.z; Ks[lcol + 3][row] = kv.w;
    }
    __syncthreads();

    float acc[4][4];
    #pragma unroll
    for (int i = 0; i < 4; i++)
        #pragma unroll
        for (int j = 0; j < 4; j++) acc[i][j] = 0.f;

    #pragma unroll 8
    for (int k = 0; k < 64; k++) {
        float a_[4], b_[4];
        #pragma unroll
        for (int ii = 0; ii < 4; ii++) a_[ii] = Qs[k][ty + ii];
        #pragma unroll
        for (int jj = 0; jj < 4; jj++) b_[jj] = Ks[k][tx + jj];
        #pragma unroll
        for (int ii = 0; ii < 4; ii++)
            #pragma unroll
            for (int jj = 0; jj < 4; jj++)
                acc[ii][jj] = fmaf(a_[ii], b_[jj], acc[ii][jj]);
    }

    #pragma unroll
    for (int ii = 0; ii < 4; ii++) {
        int i = i0 + ty + ii;
        #pragma unroll
        for (int jj = 0; jj < 4; jj++) {
            int j = j0 + tx + jj;
            float v = acc[ii][jj] * scale;
            int m = (mode == 0) ? mask[(size_t)i * Lk + j] : mask[(size_t)b * Lk + j];
            if (m == 0) v = -1e9f;
            Sp[(size_t)i * Lk + j] = v;
        }
    }
}

// -------------------- row softmax over Lk=2048, 1 block/row --------------
__global__ void __launch_bounds__(256) softmax_rows(float* __restrict__ S, int Lk)
{
    __shared__ float buf[2048];
    __shared__ float red[256];
    const size_t row = blockIdx.x;
    float* p = S + row * (size_t)Lk;
    const int tid = threadIdx.x;
    const int base = tid << 3;

    float4 v0 = *(const float4*)(p + base);
    float4 v1 = *(const float4*)(p + base + 4);
    float m = fmaxf(fmaxf(fmaxf(v0.x, v0.y), fmaxf(v0.z, v0.w)),
                    fmaxf(fmaxf(v1.x, v1.y), fmaxf(v1.z, v1.w)));
    red[tid] = m; __syncthreads();
    for (int s = 128; s > 0; s >>= 1) {
        if (tid < s) red[tid] = fmaxf(red[tid], red[tid + s]);
        __syncthreads();
    }
    const float M = red[0];
    __syncthreads();

    float e0 = expf(v0.x - M), e1 = expf(v0.y - M), e2 = expf(v0.z - M), e3 = expf(v0.w - M);
    float e4 = expf(v1.x - M), e5 = expf(v1.y - M), e6 = expf(v1.z - M), e7 = expf(v1.w - M);
    buf[base + 0] = e0; buf[base + 1] = e1; buf[base + 2] = e2; buf[base + 3] = e3;
    buf[base + 4] = e4; buf[base + 5] = e5; buf[base + 6] = e6; buf[base + 7] = e7;
    red[tid] = e0 + e1 + e2 + e3 + e4 + e5 + e6 + e7;
    __syncthreads();
    for (int s = 128; s > 0; s >>= 1) {
        if (tid < s) red[tid] += red[tid + s];
        __syncthreads();
    }
    const float inv = 1.f / red[0];

    float4 o0, o1;
    o0.x = buf[base + 0] * inv; o0.y = buf[base + 1] * inv;
    o0.z = buf[base + 2] * inv; o0.w = buf[base + 3] * inv;
    o1.x = buf[base + 4] * inv; o1.y = buf[base + 5] * inv;
    o1.z = buf[base + 6] * inv; o1.w = buf[base + 7] * inv;
    *(float4*)(p + base) = o0;
    *(float4*)(p + base + 4) = o1;
}

// -------- batched O = P @ V_h : M=Lq, N=64, K=Lk ; causal K truncation -----
__global__ void __launch_bounds__(256) attn_v(
    const float* __restrict__ P, const float* __restrict__ V,
    float* __restrict__ O, int Lq, int Lk, int causal)
{
    const int bh = blockIdx.z;
    const int b  = bh / HH;
    const int h  = bh % HH;
    const int i0 = blockIdx.y << 6;
    const int tid = threadIdx.x;
    const int ty  = (tid >> 4) << 2;
    const int tx  = (tid & 15) << 2;
    const float* Pp = P + (size_t)bh * Lq * Lk;

    __shared__ float Ps[64][65];   // [i][j]
    __shared__ float Vs[64][64];   // [j][d]
    float acc[4][4];
    #pragma unroll
    for (int i = 0; i < 4; i++)
        #pragma unroll
        for (int j = 0; j < 4; j++) acc[i][j] = 0.f;

    const int lrow = tid >> 4;
    const int lcol = (tid & 15) << 2;
    const int jend = causal ? (i0 + 64) : Lk;

    for (int j0 = 0; j0 < jend; j0 += 64) {
        #pragma unroll
        for (int r = 0; r < 4; r++) {
            int row = lrow + (r << 4);
            float4 pv = *(const float4*)(Pp + (size_t)(i0 + row) * Lk + j0 + lcol);
            Ps[row][lcol + 0] = pv.x; Ps[row][lcol + 1] = pv.y;
            Ps[row][lcol + 2] = pv.z; Ps[row][lcol + 3] = pv.w;
            float4 vv = *(const float4*)(V + (size_t)(b * Lk + j0 + row) * DD + h * DKK + lcol);
            *(float4*)&Vs[row][lcol] = vv;
        }
        __syncthreads();
        #pragma unroll 8
        for (int k = 0; k < 64; k++) {
            float a_[4], b_[4];
            #pragma unroll
            for (int ii = 0; ii < 4; ii++) a_[ii] = Ps[ty + ii][k];
            #pragma unroll
            for (int jj = 0; jj < 4; jj++) b_[jj] = Vs[k][tx + jj];
            #pragma unroll
            for (int ii = 0; ii < 4; ii++)
                #pragma unroll
                for (int jj = 0; jj < 4; jj++)
                    acc[ii][jj] = fmaf(a_[ii], b_[jj], acc[ii][jj]);
        }
        __syncthreads();
    }
    #pragma unroll
    for (int ii = 0; ii < 4; ii++)
        #pragma unroll
        for (int jj = 0; jj < 4; jj++)
            O[(size_t)(b * Lq + i0 + ty + ii) * DD + h * DKK + tx + jj] = acc[ii][jj];
}

// -------------------- out = LayerNorm(a + r) * g + beta ------------------
__global__ void __launch_bounds__(256) add_ln(
    const float* __restrict__ a, const float* __restrict__ r,
    const float* __restrict__ g, const float* __restrict__ beta,
    float* __restrict__ out)
{
    __shared__ float rs[256], rss[256];
    const size_t row = blockIdx.x;
    const int tid = threadIdx.x;
    const int c = tid << 2;
    float4 av = *(const float4*)(a + row * DD + c);
    float4 rv = *(const float4*)(r + row * DD + c);
    float x0 = av.x + rv.x, x1 = av.y + rv.y, x2 = av.z + rv.z, x3 = av.w + rv.w;
    rs[tid]  = x0 + x1 + x2 + x3;
    rss[tid] = x0 * x0 + x1 * x1 + x2 * x2 + x3 * x3;
    __syncthreads();
    for (int s = 128; s > 0; s >>= 1) {
        if (tid < s) { rs[tid] += rs[tid + s]; rss[tid] += rss[tid + s]; }
        __syncthreads();
    }
    const float mu  = rs[0] * (1.f / DD);
    const float var = rss[0] * (1.f / DD) - mu * mu;
    const float inv = rsqrtf(var + 1e-5f);
    float4 gv = *(const float4*)(g + c);
    float4 bv = *(const float4*)(beta + c);
    float4 o;
    o.x = (x0 - mu) * inv * gv.x + bv.x;
    o.y = (x1 - mu) * inv * gv.y + bv.y;
    o.z = (x2 - mu) * inv * gv.z + bv.z;
    o.w = (x3 - mu) * inv * gv.w + bv.w;
    *(float4*)(out + row * DD + c) = o;
}

// ---------------------------------------------------------------------------
extern "C" void kernel_launch(void* const* d_in, const int* in_sizes, int n_in,
                              void* d_out, int out_size)
{
    const float* x        = (const float*)d_in[0];
    const float* enc      = (const float*)d_in[1];
    const int*   tgt_mask = (const int*)d_in[2];
    const int*   src_mask = (const int*)d_in[3];
    const float* self_wq = (const float*)d_in[4],  *self_bq = (const float*)d_in[5];
    const float* self_wk = (const float*)d_in[6],  *self_bk = (const float*)d_in[7];
    const float* self_wv = (const float*)d_in[8],  *self_bv = (const float*)d_in[9];
    const float* self_wo = (const float*)d_in[10], *self_bo = (const float*)d_in[11];
    const float* cross_wq = (const float*)d_in[12], *cross_bq = (const float*)d_in[13];
    const float* cross_wk = (const float*)d_in[14], *cross_bk = (const float*)d_in[15];
    const float* cross_wv = (const float*)d_in[16], *cross_bv = (const float*)d_in[17];
    const float* cross_wo = (const float*)d_in[18], *cross_bo = (const float*)d_in[19];
    const float* ff_w1 = (const float*)d_in[20], *ff_b1 = (const float*)d_in[21];
    const float* ff_w2 = (const float*)d_in[22], *ff_b2 = (const float*)d_in[23];
    const float* n1_g = (const float*)d_in[24], *n1_b = (const float*)d_in[25];
    const float* n2_g = (const float*)d_in[26], *n2_b = (const float*)d_in[27];
    const float* n3_g = (const float*)d_in[28], *n3_b = (const float*)d_in[29];
    float* out = (float*)d_out;

    float *q, *k, *v, *attn, *tmp, *x1, *x2, *ff, *sc;
    cudaGetSymbolAddress((void**)&q,    g_q);
    cudaGetSymbolAddress((void**)&k,    g_k);
    cudaGetSymbolAddress((void**)&v,    g_v);
    cudaGetSymbolAddress((void**)&attn, g_attn);
    cudaGetSymbolAddress((void**)&tmp,  g_tmp);
    cudaGetSymbolAddress((void**)&x1,   g_x1);
    cudaGetSymbolAddress((void**)&x2,   g_x2);
    cudaGetSymbolAddress((void**)&ff,   g_ff);
    cudaGetSymbolAddress((void**)&sc,   g_sc);

    const dim3 gProj(DD / 128, MR / 128);        // 8 x 32
    const dim3 gFF1(DFFF / 128, MR / 128);       // 32 x 32
    const dim3 gSc(LSS / 64, LTT / 64, BB * HH); // 32 x 32 x 32
    const dim3 gAV(1, LTT / 64, BB * HH);
    const float scale = 0.125f;  // 1/sqrt(64)
    const int nRows = BB * HH * LTT;             // 65536 softmax rows

    // ---- self-attention ----
    sgemm<<<gProj, 256>>>(x, self_wq, self_bq, q, MR, DD, DD, 0);
    sgemm<<<gProj, 256>>>(x, self_wk, self_bk, k, MR, DD, DD, 0);
    sgemm<<<gProj, 256>>>(x, self_wv, self_bv, v, MR, DD, DD, 0);
    attn_scores<<<gSc, 256>>>(q, k, tgt_mask, sc, LTT, LTT, 0, scale);
    softmax_rows<<<nRows, 256>>>(sc, LTT);
    attn_v<<<gAV, 256>>>(sc, v, attn, LTT, LTT, 1);
    sgemm<<<gProj, 256>>>(attn, self_wo, self_bo, tmp, MR, DD, DD, 0);
    add_ln<<<MR, 256>>>(x, tmp, n1_g, n1_b, x1);

    // ---- cross-attention ----
    sgemm<<<gProj, 256>>>(x1,  cross_wq, cross_bq, q, MR, DD, DD, 0);
    sgemm<<<gProj, 256>>>(enc, cross_wk, cross_bk, k, MR, DD, DD, 0);
    sgemm<<<gProj, 256>>>(enc, cross_wv, cross_bv, v, MR, DD, DD, 0);
    attn_scores<<<gSc, 256>>>(q, k, src_mask, sc, LTT, LSS, 1, scale);
    softmax_rows<<<nRows, 256>>>(sc, LSS);
    attn_v<<<gAV, 256>>>(sc, v, attn, LTT, LSS, 0);
    sgemm<<<gProj, 256>>>(attn, cross_wo, cross_bo, tmp, MR, DD, DD, 0);
    add_ln<<<MR, 256>>>(x1, tmp, n2_g, n2_b, x2);

    // ---- feed-forward ----
    sgemm<<<gFF1, 256>>>(x2, ff_w1, ff_b1, ff, MR, DFFF, DD, 1);   // + GELU
    sgemm<<<gProj, 256>>>(ff, ff_w2, ff_b2, tmp, MR, DD, DFFF, 0);
    add_ln<<<MR, 256>>>(x2, tmp, n3_g, n3_b, out);
}

// round 7
// speedup vs baseline: 1.4168x; 1.4168x over previous
#include <cuda_runtime.h>
#include <math.h>

// Problem dims
#define BB   2
#define LTT  2048
#define LSS  2048
#define DD   1024
#define HH   16
#define DKK  64
#define DFFF 4096
#define MR   (BB*LTT)   // 4096 rows
#define BH   (BB*HH)    // 32

// ---------------- scratch (__device__ globals, no allocs) ----------------
__device__ float g_q   [(size_t)MR*DD];
__device__ float g_k   [(size_t)MR*DD];
__device__ float g_v   [(size_t)MR*DD];
__device__ float g_attn[(size_t)MR*DD];
__device__ float g_tmp [(size_t)MR*DD];
__device__ float g_x1  [(size_t)MR*DD];
__device__ float g_x2  [(size_t)MR*DD];
__device__ float g_ff  [(size_t)MR*DFFF];
__device__ float g_sc  [(size_t)BH*LTT*LSS];   // score/prob matrix

// ------------------------- tf32 helpers -----------------------------------
__device__ __forceinline__ unsigned f2tf32(float x) {
    unsigned y;
    asm("cvt.rna.tf32.f32 %0, %1;" : "=r"(y) : "f"(x));
    return y;
}

// D += A(16x8) @ B(8x8), tf32 in, fp32 accum.  row.col layout.
__device__ __forceinline__ void mma8(float* d, const unsigned* a, const unsigned* b) {
    asm volatile(
        "mma.sync.aligned.m16n8k8.row.col.f32.tf32.tf32.f32 "
        "{%0,%1,%2,%3},{%4,%5,%6,%7},{%8,%9},{%0,%1,%2,%3};\n"
        : "+f"(d[0]), "+f"(d[1]), "+f"(d[2]), "+f"(d[3])
        : "r"(a[0]), "r"(a[1]), "r"(a[2]), "r"(a[3]), "r"(b[0]), "r"(b[1]));
}

// ---------------- TF32 GEMM: C = A[M,K] @ W[K,N] + bias (+gelu) -----------
// 128x128 block tile, BK=32, 256 threads (8 warps, 2x4), warp tile 64x32.
// grid.z selects among up to 3 (W,bias,C) sets sharing the same A (fused QKV).
__global__ void __launch_bounds__(256, 2) gemm_tf32(
    const float* __restrict__ A,
    const float* __restrict__ W0, const float* __restrict__ b0, float* __restrict__ C0,
    const float* __restrict__ W1, const float* __restrict__ b1, float* __restrict__ C1,
    const float* __restrict__ W2, const float* __restrict__ b2, float* __restrict__ C2,
    int M, int N, int K, int act)
{
    const float* W = W0; const float* bias = b0; float* C = C0;
    if (blockIdx.z == 1) { W = W1; bias = b1; C = C1; }
    else if (blockIdx.z == 2) { W = W2; bias = b2; C = C2; }

    __shared__ unsigned As[128 * 36];   // [m][k], stride 36 -> conflict-free frags
    __shared__ unsigned Bs[32 * 136];   // [k][n], stride 136 -> conflict-free frags

    const int tid  = threadIdx.x;
    const int brow = blockIdx.y << 7;
    const int bcol = blockIdx.x << 7;
    const int w    = tid >> 5, lane = tid & 31;
    const int wm   = (w & 1) << 6;      // 0 / 64
    const int wn   = (w >> 1) << 5;     // 0..96
    const int lr   = lane >> 2, lc = lane & 3;

    const int arow = tid >> 1;                 // 0..127
    const int acol = (tid & 1) << 4;           // 0 / 16
    const int brw  = tid >> 3;                 // 0..31
    const int bcl  = (tid & 7) << 4;           // 0..112

    float acc[4][4][4];
    #pragma unroll
    for (int mt = 0; mt < 4; mt++)
        #pragma unroll
        for (int nt = 0; nt < 4; nt++)
            #pragma unroll
            for (int i = 0; i < 4; i++) acc[mt][nt][i] = 0.f;

    for (int k0 = 0; k0 < K; k0 += 32) {
        #pragma unroll
        for (int i = 0; i < 4; i++) {
            float4 v = *(const float4*)(A + (size_t)(brow + arow) * K + k0 + acol + i * 4);
            unsigned* dst = &As[arow * 36 + acol + i * 4];
            dst[0] = f2tf32(v.x); dst[1] = f2tf32(v.y);
            dst[2] = f2tf32(v.z); dst[3] = f2tf32(v.w);
        }
        #pragma unroll
        for (int i = 0; i < 4; i++) {
            float4 v = *(const float4*)(W + (size_t)(k0 + brw) * N + bcol + bcl + i * 4);
            unsigned* dst = &Bs[brw * 136 + bcl + i * 4];
            dst[0] = f2tf32(v.x); dst[1] = f2tf32(v.y);
            dst[2] = f2tf32(v.z); dst[3] = f2tf32(v.w);
        }
        __syncthreads();

        #pragma unroll
        for (int ks = 0; ks < 4; ks++) {
            unsigned a[4][4], bfr[4][2];
            #pragma unroll
            for (int mt = 0; mt < 4; mt++) {
                int r = wm + (mt << 4) + lr;
                int c = (ks << 3) + lc;
                a[mt][0] = As[r * 36 + c];
                a[mt][1] = As[(r + 8) * 36 + c];
                a[mt][2] = As[r * 36 + c + 4];
                a[mt][3] = As[(r + 8) * 36 + c + 4];
            }
            #pragma unroll
            for (int nt = 0; nt < 4; nt++) {
                int kk = (ks << 3) + lc;
                int c  = wn + (nt << 3) + lr;
                bfr[nt][0] = Bs[kk * 136 + c];
                bfr[nt][1] = Bs[(kk + 4) * 136 + c];
            }
            #pragma unroll
            for (int mt = 0; mt < 4; mt++)
                #pragma unroll
                for (int nt = 0; nt < 4; nt++)
                    mma8(acc[mt][nt], a[mt], bfr[nt]);
        }
        __syncthreads();
    }

    #pragma unroll
    for (int mt = 0; mt < 4; mt++) {
        #pragma unroll
        for (int nt = 0; nt < 4; nt++) {
            int r0 = brow + wm + (mt << 4) + lr;
            int c0 = bcol + wn + (nt << 3) + (lc << 1);
            float bx = bias[c0], by = bias[c0 + 1];
            float v0 = acc[mt][nt][0] + bx, v1 = acc[mt][nt][1] + by;
            float v2 = acc[mt][nt][2] + bx, v3 = acc[mt][nt][3] + by;
            if (act == 1) {
                v0 = 0.5f * v0 * (1.f + erff(v0 * 0.70710678f));
                v1 = 0.5f * v1 * (1.f + erff(v1 * 0.70710678f));
                v2 = 0.5f * v2 * (1.f + erff(v2 * 0.70710678f));
                v3 = 0.5f * v3 * (1.f + erff(v3 * 0.70710678f));
            }
            float2 lo = {v0, v1}, hi = {v2, v3};
            *(float2*)(C + (size_t)r0 * N + c0)       = lo;
            *(float2*)(C + (size_t)(r0 + 8) * N + c0) = hi;
        }
    }
}

// -------- scores: S = scale * Q @ K^T, causal mask fused, tf32 mma --------
// 128x128 S tile per block.  Causal: tiles with j0 >= i0+128 are never
// computed NOR written (softmax/attn_v never read them).
__global__ void __launch_bounds__(256, 2) attn_scores_mma(
    const float* __restrict__ Q, const float* __restrict__ Km,
    float* __restrict__ S, int Lq, int Lk, int causal, float scale)
{
    const int bh = blockIdx.z, b = bh >> 4, h = bh & 15;
    const int i0 = blockIdx.y << 7;
    const int j0 = blockIdx.x << 7;
    if (causal && j0 >= i0 + 128) return;

    __shared__ unsigned Qs[128 * 36];   // [i][k]
    __shared__ unsigned Ks[128 * 36];   // [j][k]

    const int tid = threadIdx.x;
    const int w = tid >> 5, lane = tid & 31;
    const int wm = (w & 1) << 6, wn = (w >> 1) << 5;
    const int lr = lane >> 2, lc = lane & 3;
    const int row = tid >> 1;
    const int col = (tid & 1) << 4;

    float acc[4][4][4];
    #pragma unroll
    for (int mt = 0; mt < 4; mt++)
        #pragma unroll
        for (int nt = 0; nt < 4; nt++)
            #pragma unroll
            for (int i = 0; i < 4; i++) acc[mt][nt][i] = 0.f;

    for (int k0 = 0; k0 < DKK; k0 += 32) {
        #pragma unroll
        for (int i = 0; i < 4; i++) {
            float4 qv = *(const float4*)(Q + (size_t)(b * Lq + i0 + row) * DD + h * DKK + k0 + col + i * 4);
            unsigned* qd = &Qs[row * 36 + col + i * 4];
            qd[0] = f2tf32(qv.x); qd[1] = f2tf32(qv.y);
            qd[2] = f2tf32(qv.z); qd[3] = f2tf32(qv.w);
            float4 kv = *(const float4*)(Km + (size_t)(b * Lk + j0 + row) * DD + h * DKK + k0 + col + i * 4);
            unsigned* kd = &Ks[row * 36 + col + i * 4];
            kd[0] = f2tf32(kv.x); kd[1] = f2tf32(kv.y);
            kd[2] = f2tf32(kv.z); kd[3] = f2tf32(kv.w);
        }
        __syncthreads();

        #pragma unroll
        for (int ks = 0; ks < 4; ks++) {
            unsigned a[4][4], bfr[4][2];
            #pragma unroll
            for (int mt = 0; mt < 4; mt++) {
                int r = wm + (mt << 4) + lr;
                int c = (ks << 3) + lc;
                a[mt][0] = Qs[r * 36 + c];
                a[mt][1] = Qs[(r + 8) * 36 + c];
                a[mt][2] = Qs[r * 36 + c + 4];
                a[mt][3] = Qs[(r + 8) * 36 + c + 4];
            }
            #pragma unroll
            for (int nt = 0; nt < 4; nt++) {
                int n = wn + (nt << 3) + lr;
                int c = (ks << 3) + lc;
                bfr[nt][0] = Ks[n * 36 + c];
                bfr[nt][1] = Ks[n * 36 + c + 4];
            }
            #pragma unroll
            for (int mt = 0; mt < 4; mt++)
                #pragma unroll
                for (int nt = 0; nt < 4; nt++)
                    mma8(acc[mt][nt], a[mt], bfr[nt]);
        }
        __syncthreads();
    }

    float* Sp = S + (size_t)bh * Lq * Lk;
    #pragma unroll
    for (int mt = 0; mt < 4; mt++) {
        #pragma unroll
        for (int nt = 0; nt < 4; nt++) {
            int i = i0 + wm + (mt << 4) + lr;
            int j = j0 + wn + (nt << 3) + (lc << 1);
            float v0 = acc[mt][nt][0] * scale, v1 = acc[mt][nt][1] * scale;
            float v2 = acc[mt][nt][2] * scale, v3 = acc[mt][nt][3] * scale;
            if (causal) {
                if (j     > i)     v0 = -1e9f;
                if (j + 1 > i)     v1 = -1e9f;
                if (j     > i + 8) v2 = -1e9f;
                if (j + 1 > i + 8) v3 = -1e9f;
            }
            float2 lo = {v0, v1}, hi = {v2, v3};
            *(float2*)(Sp + (size_t)i * Lk + j)       = lo;
            *(float2*)(Sp + (size_t)(i + 8) * Lk + j) = hi;
        }
    }
}

// --------------- row softmax, causal-truncated length ---------------------
__global__ void __launch_bounds__(256) softmax_rows(
    float* __restrict__ S, int Lq, int Lk, int causal)
{
    const int row = blockIdx.x;            // bh*Lq + i
    const int i = row & (Lq - 1);
    const int n = causal ? (((i >> 7) + 1) << 7) : Lk;
    float* p = S + (size_t)row * Lk;

    __shared__ float buf[2048];
    __shared__ float red[256];
    const int tid = threadIdx.x;

    float m = -3.4e38f;
    for (int c = tid << 2; c < n; c += 1024) {
        float4 v = *(const float4*)(p + c);
        *(float4*)(buf + c) = v;
        m = fmaxf(m, fmaxf(fmaxf(v.x, v.y), fmaxf(v.z, v.w)));
    }
    red[tid] = m; __syncthreads();
    for (int s = 128; s > 0; s >>= 1) {
        if (tid < s) red[tid] = fmaxf(red[tid], red[tid + s]);
        __syncthreads();
    }
    const float M = red[0];
    __syncthreads();

    float sum = 0.f;
    for (int c = tid << 2; c < n; c += 1024) {
        float4 v = *(const float4*)(buf + c);
        v.x = expf(v.x - M); v.y = expf(v.y - M);
        v.z = expf(v.z - M); v.w = expf(v.w - M);
        *(float4*)(buf + c) = v;
        sum += v.x + v.y + v.z + v.w;
    }
    red[tid] = sum; __syncthreads();
    for (int s = 128; s > 0; s >>= 1) {
        if (tid < s) red[tid] += red[tid + s];
        __syncthreads();
    }
    const float inv = 1.f / red[0];

    for (int c = tid << 2; c < n; c += 1024) {
        float4 v = *(const float4*)(buf + c);
        v.x *= inv; v.y *= inv; v.z *= inv; v.w *= inv;
        *(float4*)(p + c) = v;
    }
}

// --------- O = P @ V_h : 128 rows x 64 cols per block, tf32 mma -----------
__global__ void __launch_bounds__(256, 2) attn_v_mma(
    const float* __restrict__ P, const float* __restrict__ V,
    float* __restrict__ O, int Lq, int Lk, int causal)
{
    const int bh = blockIdx.y, b = bh >> 4, h = bh & 15;
    const int i0 = blockIdx.x << 7;
    const float* Pp = P + (size_t)bh * Lq * Lk;

    __shared__ unsigned Ps[128 * 36];  // [i][j-chunk]
    __shared__ unsigned Vs[32 * 72];   // [j][d]

    const int tid = threadIdx.x;
    const int w = tid >> 5, lane = tid & 31;
    const int wm = (w & 3) << 5;       // 0..96 (4 warps over 128 rows)
    const int wn = (w >> 2) << 5;      // 0 / 32 (2 warps over 64 cols)
    const int lr = lane >> 2, lc = lane & 3;
    const int prow = tid >> 1, pcol = (tid & 1) << 4;
    const int vrow = tid >> 3, vcol = (tid & 7) << 3;

    float acc[2][4][4];
    #pragma unroll
    for (int mt = 0; mt < 2; mt++)
        #pragma unroll
        for (int nt = 0; nt < 4; nt++)
            #pragma unroll
            for (int i = 0; i < 4; i++) acc[mt][nt][i] = 0.f;

    const int jend = causal ? (i0 + 128) : Lk;
    for (int j0 = 0; j0 < jend; j0 += 32) {
        #pragma unroll
        for (int i = 0; i < 4; i++) {
            float4 v = *(const float4*)(Pp + (size_t)(i0 + prow) * Lk + j0 + pcol + i * 4);
            unsigned* dst = &Ps[prow * 36 + pcol + i * 4];
            dst[0] = f2tf32(v.x); dst[1] = f2tf32(v.y);
            dst[2] = f2tf32(v.z); dst[3] = f2tf32(v.w);
        }
        #pragma unroll
        for (int i = 0; i < 2; i++) {
            float4 v = *(const float4*)(V + (size_t)(b * Lk + j0 + vrow) * DD + h * DKK + vcol + i * 4);
            unsigned* dst = &Vs[vrow * 72 + vcol + i * 4];
            dst[0] = f2tf32(v.x); dst[1] = f2tf32(v.y);
            dst[2] = f2tf32(v.z); dst[3] = f2tf32(v.w);
        }
        __syncthreads();

        #pragma unroll
        for (int ks = 0; ks < 4; ks++) {
            unsigned a[2][4], bfr[4][2];
            #pragma unroll
            for (int mt = 0; mt < 2; mt++) {
                int r = wm + (mt << 4) + lr;
                int c = (ks << 3) + lc;
                a[mt][0] = Ps[r * 36 + c];
                a[mt][1] = Ps[(r + 8) * 36 + c];
                a[mt][2] = Ps[r * 36 + c + 4];
                a[mt][3] = Ps[(r + 8) * 36 + c + 4];
            }
            #pragma unroll
            for (int nt = 0; nt < 4; nt++) {
                int kk = (ks << 3) + lc;
                int c  = wn + (nt << 3) + lr;
                bfr[nt][0] = Vs[kk * 72 + c];
                bfr[nt][1] = Vs[(kk + 4) * 72 + c];
            }
            #pragma unroll
            for (int mt = 0; mt < 2; mt++)
                #pragma unroll
                for (int nt = 0; nt < 4; nt++)
                    mma8(acc[mt][nt], a[mt], bfr[nt]);
        }
        __syncthreads();
    }

    #pragma unroll
    for (int mt = 0; mt < 2; mt++) {
        #pragma unroll
        for (int nt = 0; nt < 4; nt++) {
            int r0 = i0 + wm + (mt << 4) + lr;
            int c0 = wn + (nt << 3) + (lc << 1);
            float2 lo = {acc[mt][nt][0], acc[mt][nt][1]};
            float2 hi = {acc[mt][nt][2], acc[mt][nt][3]};
            *(float2*)(O + (size_t)(b * Lq + r0) * DD + h * DKK + c0)       = lo;
            *(float2*)(O + (size_t)(b * Lq + r0 + 8) * DD + h * DKK + c0)   = hi;
        }
    }
}

// -------------------- out = LayerNorm(a + r) * g + beta ------------------
__global__ void __launch_bounds__(256) add_ln(
    const float* __restrict__ a, const float* __restrict__ r,
    const float* __restrict__ g, const float* __restrict__ beta,
    float* __restrict__ out)
{
    __shared__ float rs[256], rss[256];
    const size_t row = blockIdx.x;
    const int tid = threadIdx.x;
    const int c = tid << 2;
    float4 av = *(const float4*)(a + row * DD + c);
    float4 rv = *(const float4*)(r + row * DD + c);
    float x0 = av.x + rv.x, x1 = av.y + rv.y, x2 = av.z + rv.z, x3 = av.w + rv.w;
    rs[tid]  = x0 + x1 + x2 + x3;
    rss[tid] = x0 * x0 + x1 * x1 + x2 * x2 + x3 * x3;
    __syncthreads();
    for (int s = 128; s > 0; s >>= 1) {
        if (tid < s) { rs[tid] += rs[tid + s]; rss[tid] += rss[tid + s]; }
        __syncthreads();
    }
    const float mu  = rs[0] * (1.f / DD);
    const float var = rss[0] * (1.f / DD) - mu * mu;
    const float inv = rsqrtf(var + 1e-5f);
    float4 gv = *(const float4*)(g + c);
    float4 bv = *(const float4*)(beta + c);
    float4 o;
    o.x = (x0 - mu) * inv * gv.x + bv.x;
    o.y = (x1 - mu) * inv * gv.y + bv.y;
    o.z = (x2 - mu) * inv * gv.z + bv.z;
    o.w = (x3 - mu) * inv * gv.w + bv.w;
    *(float4*)(out + row * DD + c) = o;
}

// ---------------------------------------------------------------------------
extern "C" void kernel_launch(void* const* d_in, const int* in_sizes, int n_in,
                              void* d_out, int out_size)
{
    const float* x        = (const float*)d_in[0];
    const float* enc      = (const float*)d_in[1];
    const float* self_wq = (const float*)d_in[4],  *self_bq = (const float*)d_in[5];
    const float* self_wk = (const float*)d_in[6],  *self_bk = (const float*)d_in[7];
    const float* self_wv = (const float*)d_in[8],  *self_bv = (const float*)d_in[9];
    const float* self_wo = (const float*)d_in[10], *self_bo = (const float*)d_in[11];
    const float* cross_wq = (const float*)d_in[12], *cross_bq = (const float*)d_in[13];
    const float* cross_wk = (const float*)d_in[14], *cross_bk = (const float*)d_in[15];
    const float* cross_wv = (const float*)d_in[16], *cross_bv = (const float*)d_in[17];
    const float* cross_wo = (const float*)d_in[18], *cross_bo = (const float*)d_in[19];
    const float* ff_w1 = (const float*)d_in[20], *ff_b1 = (const float*)d_in[21];
    const float* ff_w2 = (const float*)d_in[22], *ff_b2 = (const float*)d_in[23];
    const float* n1_g = (const float*)d_in[24], *n1_b = (const float*)d_in[25];
    const float* n2_g = (const float*)d_in[26], *n2_b = (const float*)d_in[27];
    const float* n3_g = (const float*)d_in[28], *n3_b = (const float*)d_in[29];
    float* out = (float*)d_out;

    float *q, *k, *v, *attn, *tmp, *x1, *x2, *ff, *sc;
    cudaGetSymbolAddress((void**)&q,    g_q);
    cudaGetSymbolAddress((void**)&k,    g_k);
    cudaGetSymbolAddress((void**)&v,    g_v);
    cudaGetSymbolAddress((void**)&attn, g_attn);
    cudaGetSymbolAddress((void**)&tmp,  g_tmp);
    cudaGetSymbolAddress((void**)&x1,   g_x1);
    cudaGetSymbolAddress((void**)&x2,   g_x2);
    cudaGetSymbolAddress((void**)&ff,   g_ff);
    cudaGetSymbolAddress((void**)&sc,   g_sc);

    const dim3 gQKV(DD / 128, MR / 128, 3);
    const dim3 gKV (DD / 128, MR / 128, 2);
    const dim3 gP  (DD / 128, MR / 128, 1);
    const dim3 gFF1(DFFF / 128, MR / 128, 1);
    const dim3 gSc (LSS / 128, LTT / 128, BH);
    const dim3 gAV (LTT / 128, BH);
    const float scale = 0.125f;              // 1/sqrt(64)
    const int nRows = BH * LTT;

    // ---- self-attention (causal) ----
    gemm_tf32<<<gQKV, 256>>>(x, self_wq, self_bq, q, self_wk, self_bk, k,
                             self_wv, self_bv, v, MR, DD, DD, 0);
    attn_scores_mma<<<gSc, 256>>>(q, k, sc, LTT, LTT, 1, scale);
    softmax_rows<<<nRows, 256>>>(sc, LTT, LTT, 1);
    attn_v_mma<<<gAV, 256>>>(sc, v, attn, LTT, LTT, 1);
    gemm_tf32<<<gP, 256>>>(attn, self_wo, self_bo, tmp,
                           self_wo, self_bo, tmp, self_wo, self_bo, tmp, MR, DD, DD, 0);
    add_ln<<<MR, 256>>>(x, tmp, n1_g, n1_b, x1);

    // ---- cross-attention (no mask) ----
    gemm_tf32<<<gP, 256>>>(x1, cross_wq, cross_bq, q,
                           cross_wq, cross_bq, q, cross_wq, cross_bq, q, MR, DD, DD, 0);
    gemm_tf32<<<gKV, 256>>>(enc, cross_wk, cross_bk, k, cross_wv, cross_bv, v,
                            cross_wv, cross_bv, v, MR, DD, DD, 0);
    attn_scores_mma<<<gSc, 256>>>(q, k, sc, LTT, LSS, 0, scale);
    softmax_rows<<<nRows, 256>>>(sc, LTT, LSS, 0);
    attn_v_mma<<<gAV, 256>>>(sc, v, attn, LTT, LSS, 0);
    gemm_tf32<<<gP, 256>>>(attn, cross_wo, cross_bo, tmp,
                           cross_wo, cross_bo, tmp, cross_wo, cross_bo, tmp, MR, DD, DD, 0);
    add_ln<<<MR, 256>>>(x1, tmp, n2_g, n2_b, x2);

    // ---- feed-forward ----
    gemm_tf32<<<gFF1, 256>>>(x2, ff_w1, ff_b1, ff,
                             ff_w1, ff_b1, ff, ff_w1, ff_b1, ff, MR, DFFF, DD, 1);
    gemm_tf32<<<gP, 256>>>(ff, ff_w2, ff_b2, tmp,
                           ff_w2, ff_b2, tmp, ff_w2, ff_b2, tmp, MR, DD, DFFF, 0);
    add_ln<<<MR, 256>>>(x2, tmp, n3_g, n3_b, out);
}

// round 8
// speedup vs baseline: 2.7147x; 1.9161x over previous
#include <cuda_runtime.h>
#include <math.h>

// Problem dims
#define BB   2
#define LTT  2048
#define LSS  2048
#define DD   1024
#define HH   16
#define DKK  64
#define DFFF 4096
#define MR   (BB*LTT)   // 4096 rows
#define BH   (BB*HH)    // 32

// ---------------- scratch (__device__ globals, no allocs) ----------------
__device__ float g_q   [(size_t)MR*DD];
__device__ float g_k   [(size_t)MR*DD];
__device__ float g_v   [(size_t)MR*DD];
__device__ float g_attn[(size_t)MR*DD];
__device__ float g_tmp [(size_t)MR*DD];
__device__ float g_x1  [(size_t)MR*DD];
__device__ float g_x2  [(size_t)MR*DD];
__device__ float g_ff  [(size_t)MR*DFFF];

// ------------------------- tf32 helpers -----------------------------------
__device__ __forceinline__ unsigned f2tf32(float x) {
    unsigned y;
    asm("cvt.rna.tf32.f32 %0, %1;" : "=r"(y) : "f"(x));
    return y;
}

// D += A(16x8) @ B(8x8), tf32 in, fp32 accum.  row.col layout.
__device__ __forceinline__ void mma8(float* d, const unsigned* a, const unsigned* b) {
    asm volatile(
        "mma.sync.aligned.m16n8k8.row.col.f32.tf32.tf32.f32 "
        "{%0,%1,%2,%3},{%4,%5,%6,%7},{%8,%9},{%0,%1,%2,%3};\n"
        : "+f"(d[0]), "+f"(d[1]), "+f"(d[2]), "+f"(d[3])
        : "r"(a[0]), "r"(a[1]), "r"(a[2]), "r"(a[3]), "r"(b[0]), "r"(b[1]));
}

// ---------------- TF32 GEMM: C = A[M,K] @ W[K,N] + bias (+gelu) -----------
// 128x128 block tile, BK=32, 256 threads (8 warps, 2x4), warp tile 64x32.
// grid.z selects among up to 3 (W,bias,C) sets sharing the same A (fused QKV).
__global__ void __launch_bounds__(256, 2) gemm_tf32(
    const float* __restrict__ A,
    const float* __restrict__ W0, const float* __restrict__ b0, float* __restrict__ C0,
    const float* __restrict__ W1, const float* __restrict__ b1, float* __restrict__ C1,
    const float* __restrict__ W2, const float* __restrict__ b2, float* __restrict__ C2,
    int M, int N, int K, int act)
{
    const float* W = W0; const float* bias = b0; float* C = C0;
    if (blockIdx.z == 1) { W = W1; bias = b1; C = C1; }
    else if (blockIdx.z == 2) { W = W2; bias = b2; C = C2; }

    __shared__ unsigned As[128 * 36];   // [m][k]
    __shared__ unsigned Bs[32 * 136];   // [k][n]

    const int tid  = threadIdx.x;
    const int brow = blockIdx.y << 7;
    const int bcol = blockIdx.x << 7;
    const int w    = tid >> 5, lane = tid & 31;
    const int wm   = (w & 1) << 6;
    const int wn   = (w >> 1) << 5;
    const int lr   = lane >> 2, lc = lane & 3;

    const int arow = tid >> 1;
    const int acol = (tid & 1) << 4;
    const int brw  = tid >> 3;
    const int bcl  = (tid & 7) << 4;

    float acc[4][4][4];
    #pragma unroll
    for (int mt = 0; mt < 4; mt++)
        #pragma unroll
        for (int nt = 0; nt < 4; nt++)
            #pragma unroll
            for (int i = 0; i < 4; i++) acc[mt][nt][i] = 0.f;

    for (int k0 = 0; k0 < K; k0 += 32) {
        #pragma unroll
        for (int i = 0; i < 4; i++) {
            float4 v = *(const float4*)(A + (size_t)(brow + arow) * K + k0 + acol + i * 4);
            unsigned* dst = &As[arow * 36 + acol + i * 4];
            dst[0] = f2tf32(v.x); dst[1] = f2tf32(v.y);
            dst[2] = f2tf32(v.z); dst[3] = f2tf32(v.w);
        }
        #pragma unroll
        for (int i = 0; i < 4; i++) {
            float4 v = *(const float4*)(W + (size_t)(k0 + brw) * N + bcol + bcl + i * 4);
            unsigned* dst = &Bs[brw * 136 + bcl + i * 4];
            dst[0] = f2tf32(v.x); dst[1] = f2tf32(v.y);
            dst[2] = f2tf32(v.z); dst[3] = f2tf32(v.w);
        }
        __syncthreads();

        #pragma unroll
        for (int ks = 0; ks < 4; ks++) {
            unsigned a[4][4], bfr[4][2];
            #pragma unroll
            for (int mt = 0; mt < 4; mt++) {
                int r = wm + (mt << 4) + lr;
                int c = (ks << 3) + lc;
                a[mt][0] = As[r * 36 + c];
                a[mt][1] = As[(r + 8) * 36 + c];
                a[mt][2] = As[r * 36 + c + 4];
                a[mt][3] = As[(r + 8) * 36 + c + 4];
            }
            #pragma unroll
            for (int nt = 0; nt < 4; nt++) {
                int kk = (ks << 3) + lc;
                int c  = wn + (nt << 3) + lr;
                bfr[nt][0] = Bs[kk * 136 + c];
                bfr[nt][1] = Bs[(kk + 4) * 136 + c];
            }
            #pragma unroll
            for (int mt = 0; mt < 4; mt++)
                #pragma unroll
                for (int nt = 0; nt < 4; nt++)
                    mma8(acc[mt][nt], a[mt], bfr[nt]);
        }
        __syncthreads();
    }

    #pragma unroll
    for (int mt = 0; mt < 4; mt++) {
        #pragma unroll
        for (int nt = 0; nt < 4; nt++) {
            int r0 = brow + wm + (mt << 4) + lr;
            int c0 = bcol + wn + (nt << 3) + (lc << 1);
            float bx = bias[c0], by = bias[c0 + 1];
            float v0 = acc[mt][nt][0] + bx, v1 = acc[mt][nt][1] + by;
            float v2 = acc[mt][nt][2] + bx, v3 = acc[mt][nt][3] + by;
            if (act == 1) {
                v0 = 0.5f * v0 * (1.f + erff(v0 * 0.70710678f));
                v1 = 0.5f * v1 * (1.f + erff(v1 * 0.70710678f));
                v2 = 0.5f * v2 * (1.f + erff(v2 * 0.70710678f));
                v3 = 0.5f * v3 * (1.f + erff(v3 * 0.70710678f));
            }
            float2 lo = {v0, v1}, hi = {v2, v3};
            *(float2*)(C + (size_t)r0 * N + c0)       = lo;
            *(float2*)(C + (size_t)(r0 + 8) * N + c0) = hi;
        }
    }
}

// ---------------- fused flash attention ------------------------------------
// O = softmax(scale * Q @ K^T [+causal mask]) @ V, one kernel, no gmem S.
// Block: 128 threads (4 warps), Q tile = 64 rows, KV tile = 64 per iter.
// Warp w owns rows [w*16, w*16+16) -> online-softmax stats are warp-local
// (quad shuffles only). P staged through warp-private smem for the 2nd mma.
// smem words:  Qs [64][68] | Ks [64][68] | Vs [64][72] | Ps [64][68]
#define FA_SMEM_WORDS (4352 + 4352 + 4608 + 4352)
#define FA_SMEM_BYTES (FA_SMEM_WORDS * 4)

__global__ void __launch_bounds__(128) flash_attn(
    const float* __restrict__ Q, const float* __restrict__ Km,
    const float* __restrict__ V, float* __restrict__ O,
    int Lq, int Lk, int causal, float scale)
{
    extern __shared__ unsigned sm[];
    unsigned* Qs = sm;
    unsigned* Ks = sm + 4352;
    unsigned* Vs = sm + 8704;
    unsigned* Ps = sm + 13312;

    const int bh = blockIdx.y, b = bh >> 4, h = bh & 15;
    const int i0 = (gridDim.x - 1 - blockIdx.x) << 6;   // heavy tiles first
    const int tid = threadIdx.x;
    const int w = tid >> 5, lane = tid & 31;
    const int lr = lane >> 2, lc = lane & 3;

    // ---- load Q tile once, scale folded in ----
    for (int idx = tid; idx < 1024; idx += 128) {
        int r = idx >> 4, c = (idx & 15) << 2;
        float4 v = *(const float4*)(Q + (size_t)(b * Lq + i0 + r) * DD + h * DKK + c);
        unsigned* d = &Qs[r * 68 + c];
        d[0] = f2tf32(v.x * scale); d[1] = f2tf32(v.y * scale);
        d[2] = f2tf32(v.z * scale); d[3] = f2tf32(v.w * scale);
    }

    float o[8][4];
    #pragma unroll
    for (int nt = 0; nt < 8; nt++)
        #pragma unroll
        for (int i = 0; i < 4; i++) o[nt][i] = 0.f;
    float m0 = -1e30f, m1 = -1e30f, l0 = 0.f, l1 = 0.f;

    const int r = (w << 4) + lr;            // warp-local A-frag row
    const int jend = causal ? (i0 + 64) : Lk;

    for (int j0 = 0; j0 < jend; j0 += 64) {
        __syncthreads();                     // prev iter done before overwrite
        for (int idx = tid; idx < 1024; idx += 128) {
            int rr = idx >> 4, c = (idx & 15) << 2;
            float4 kv = *(const float4*)(Km + (size_t)(b * Lk + j0 + rr) * DD + h * DKK + c);
            unsigned* kd = &Ks[rr * 68 + c];
            kd[0] = f2tf32(kv.x); kd[1] = f2tf32(kv.y);
            kd[2] = f2tf32(kv.z); kd[3] = f2tf32(kv.w);
            float4 vv = *(const float4*)(V + (size_t)(b * Lk + j0 + rr) * DD + h * DKK + c);
            unsigned* vd = &Vs[rr * 72 + c];
            vd[0] = f2tf32(vv.x); vd[1] = f2tf32(vv.y);
            vd[2] = f2tf32(vv.z); vd[3] = f2tf32(vv.w);
        }
        __syncthreads();

        // ---- S = Qs @ Ks^T ----
        float s[8][4];
        #pragma unroll
        for (int nt = 0; nt < 8; nt++)
            #pragma unroll
            for (int i = 0; i < 4; i++) s[nt][i] = 0.f;

        #pragma unroll
        for (int ks = 0; ks < 8; ks++) {
            unsigned a[4];
            int c = (ks << 3) + lc;
            a[0] = Qs[r * 68 + c];
            a[1] = Qs[(r + 8) * 68 + c];
            a[2] = Qs[r * 68 + c + 4];
            a[3] = Qs[(r + 8) * 68 + c + 4];
            #pragma unroll
            for (int nt = 0; nt < 8; nt++) {
                unsigned bb[2];
                int n = (nt << 3) + lr;
                bb[0] = Ks[n * 68 + c];
                bb[1] = Ks[n * 68 + c + 4];
                mma8(s[nt], a, bb);
            }
        }

        // ---- causal mask (diagonal tile only) ----
        if (causal && j0 + 64 > i0) {
            int ig = i0 + r;
            #pragma unroll
            for (int nt = 0; nt < 8; nt++) {
                int jg = j0 + (nt << 3) + (lc << 1);
                if (jg     > ig)     s[nt][0] = -1e30f;
                if (jg + 1 > ig)     s[nt][1] = -1e30f;
                if (jg     > ig + 8) s[nt][2] = -1e30f;
                if (jg + 1 > ig + 8) s[nt][3] = -1e30f;
            }
        }

        // ---- online softmax (rows lr / lr+8 of this warp strip) ----
        float mx0 = -1e30f, mx1 = -1e30f;
        #pragma unroll
        for (int nt = 0; nt < 8; nt++) {
            mx0 = fmaxf(mx0, fmaxf(s[nt][0], s[nt][1]));
            mx1 = fmaxf(mx1, fmaxf(s[nt][2], s[nt][3]));
        }
        mx0 = fmaxf(mx0, __shfl_xor_sync(0xffffffffu, mx0, 1));
        mx0 = fmaxf(mx0, __shfl_xor_sync(0xffffffffu, mx0, 2));
        mx1 = fmaxf(mx1, __shfl_xor_sync(0xffffffffu, mx1, 1));
        mx1 = fmaxf(mx1, __shfl_xor_sync(0xffffffffu, mx1, 2));

        float mn0 = fmaxf(m0, mx0), mn1 = fmaxf(m1, mx1);
        float al0 = __expf(m0 - mn0), al1 = __expf(m1 - mn1);
        m0 = mn0; m1 = mn1;

        float sum0 = 0.f, sum1 = 0.f;
        #pragma unroll
        for (int nt = 0; nt < 8; nt++) {
            float p0 = __expf(s[nt][0] - mn0), p1 = __expf(s[nt][1] - mn0);
            float p2 = __expf(s[nt][2] - mn1), p3 = __expf(s[nt][3] - mn1);
            sum0 += p0 + p1; sum1 += p2 + p3;
            int c = (nt << 3) + (lc << 1);
            Ps[r * 68 + c]           = f2tf32(p0);
            Ps[r * 68 + c + 1]       = f2tf32(p1);
            Ps[(r + 8) * 68 + c]     = f2tf32(p2);
            Ps[(r + 8) * 68 + c + 1] = f2tf32(p3);
            o[nt][0] *= al0; o[nt][1] *= al0;
            o[nt][2] *= al1; o[nt][3] *= al1;
        }
        sum0 += __shfl_xor_sync(0xffffffffu, sum0, 1);
        sum0 += __shfl_xor_sync(0xffffffffu, sum0, 2);
        sum1 += __shfl_xor_sync(0xffffffffu, sum1, 1);
        sum1 += __shfl_xor_sync(0xffffffffu, sum1, 2);
        l0 = l0 * al0 + sum0;
        l1 = l1 * al1 + sum1;
        __syncwarp();                        // Ps visible within warp

        // ---- O += P @ V ----
        #pragma unroll
        for (int ks = 0; ks < 8; ks++) {
            unsigned a[4];
            int c = (ks << 3) + lc;          // shared k index
            a[0] = Ps[r * 68 + c];
            a[1] = Ps[(r + 8) * 68 + c];
            a[2] = Ps[r * 68 + c + 4];
            a[3] = Ps[(r + 8) * 68 + c + 4];
            #pragma unroll
            for (int nt = 0; nt < 8; nt++) {
                unsigned bb[2];
                int n = (nt << 3) + lr;
                bb[0] = Vs[c * 72 + n];
                bb[1] = Vs[(c + 4) * 72 + n];
                mma8(o[nt], a, bb);
            }
        }
    }

    // ---- normalize + store ----
    const float inv0 = 1.f / l0, inv1 = 1.f / l1;
    const int ig = b * Lq + i0 + r;
    #pragma unroll
    for (int nt = 0; nt < 8; nt++) {
        int c = h * DKK + (nt << 3) + (lc << 1);
        float2 lo = {o[nt][0] * inv0, o[nt][1] * inv0};
        float2 hi = {o[nt][2] * inv1, o[nt][3] * inv1};
        *(float2*)(O + (size_t)ig * DD + c)       = lo;
        *(float2*)(O + (size_t)(ig + 8) * DD + c) = hi;
    }
}

// -------------------- out = LayerNorm(a + r) * g + beta ------------------
__global__ void __launch_bounds__(256) add_ln(
    const float* __restrict__ a, const float* __restrict__ r,
    const float* __restrict__ g, const float* __restrict__ beta,
    float* __restrict__ out)
{
    __shared__ float rs[256], rss[256];
    const size_t row = blockIdx.x;
    const int tid = threadIdx.x;
    const int c = tid << 2;
    float4 av = *(const float4*)(a + row * DD + c);
    float4 rv = *(const float4*)(r + row * DD + c);
    float x0 = av.x + rv.x, x1 = av.y + rv.y, x2 = av.z + rv.z, x3 = av.w + rv.w;
    rs[tid]  = x0 + x1 + x2 + x3;
    rss[tid] = x0 * x0 + x1 * x1 + x2 * x2 + x3 * x3;
    __syncthreads();
    for (int s = 128; s > 0; s >>= 1) {
        if (tid < s) { rs[tid] += rs[tid + s]; rss[tid] += rss[tid + s]; }
        __syncthreads();
    }
    const float mu  = rs[0] * (1.f / DD);
    const float var = rss[0] * (1.f / DD) - mu * mu;
    const float inv = rsqrtf(var + 1e-5f);
    float4 gv = *(const float4*)(g + c);
    float4 bv = *(const float4*)(beta + c);
    float4 o;
    o.x = (x0 - mu) * inv * gv.x + bv.x;
    o.y = (x1 - mu) * inv * gv.y + bv.y;
    o.z = (x2 - mu) * inv * gv.z + bv.z;
    o.w = (x3 - mu) * inv * gv.w + bv.w;
    *(float4*)(out + row * DD + c) = o;
}

// ---------------------------------------------------------------------------
extern "C" void kernel_launch(void* const* d_in, const int* in_sizes, int n_in,
                              void* d_out, int out_size)
{
    const float* x        = (const float*)d_in[0];
    const float* enc      = (const float*)d_in[1];
    const float* self_wq = (const float*)d_in[4],  *self_bq = (const float*)d_in[5];
    const float* self_wk = (const float*)d_in[6],  *self_bk = (const float*)d_in[7];
    const float* self_wv = (const float*)d_in[8],  *self_bv = (const float*)d_in[9];
    const float* self_wo = (const float*)d_in[10], *self_bo = (const float*)d_in[11];
    const float* cross_wq = (const float*)d_in[12], *cross_bq = (const float*)d_in[13];
    const float* cross_wk = (const float*)d_in[14], *cross_bk = (const float*)d_in[15];
    const float* cross_wv = (const float*)d_in[16], *cross_bv = (const float*)d_in[17];
    const float* cross_wo = (const float*)d_in[18], *cross_bo = (const float*)d_in[19];
    const float* ff_w1 = (const float*)d_in[20], *ff_b1 = (const float*)d_in[21];
    const float* ff_w2 = (const float*)d_in[22], *ff_b2 = (const float*)d_in[23];
    const float* n1_g = (const float*)d_in[24], *n1_b = (const float*)d_in[25];
    const float* n2_g = (const float*)d_in[26], *n2_b = (const float*)d_in[27];
    const float* n3_g = (const float*)d_in[28], *n3_b = (const float*)d_in[29];
    float* out = (float*)d_out;

    float *q, *k, *v, *attn, *tmp, *x1, *x2, *ff;
    cudaGetSymbolAddress((void**)&q,    g_q);
    cudaGetSymbolAddress((void**)&k,    g_k);
    cudaGetSymbolAddress((void**)&v,    g_v);
    cudaGetSymbolAddress((void**)&attn, g_attn);
    cudaGetSymbolAddress((void**)&tmp,  g_tmp);
    cudaGetSymbolAddress((void**)&x1,   g_x1);
    cudaGetSymbolAddress((void**)&x2,   g_x2);
    cudaGetSymbolAddress((void**)&ff,   g_ff);

    cudaFuncSetAttribute(flash_attn,
                         cudaFuncAttributeMaxDynamicSharedMemorySize, FA_SMEM_BYTES);

    const dim3 gQKV(DD / 128, MR / 128, 3);
    const dim3 gKV (DD / 128, MR / 128, 2);
    const dim3 gP  (DD / 128, MR / 128, 1);
    const dim3 gFF1(DFFF / 128, MR / 128, 1);
    const dim3 gFA (LTT / 64, BH);
    const float scale = 0.125f;              // 1/sqrt(64)

    // ---- self-attention (causal) ----
    gemm_tf32<<<gQKV, 256>>>(x, self_wq, self_bq, q, self_wk, self_bk, k,
                             self_wv, self_bv, v, MR, DD, DD, 0);
    flash_attn<<<gFA, 128, FA_SMEM_BYTES>>>(q, k, v, attn, LTT, LTT, 1, scale);
    gemm_tf32<<<gP, 256>>>(attn, self_wo, self_bo, tmp,
                           self_wo, self_bo, tmp, self_wo, self_bo, tmp, MR, DD, DD, 0);
    add_ln<<<MR, 256>>>(x, tmp, n1_g, n1_b, x1);

    // ---- cross-attention (no mask) ----
    gemm_tf32<<<gP, 256>>>(x1, cross_wq, cross_bq, q,
                           cross_wq, cross_bq, q, cross_wq, cross_bq, q, MR, DD, DD, 0);
    gemm_tf32<<<gKV, 256>>>(enc, cross_wk, cross_bk, k, cross_wv, cross_bv, v,
                            cross_wv, cross_bv, v, MR, DD, DD, 0);
    flash_attn<<<gFA, 128, FA_SMEM_BYTES>>>(q, k, v, attn, LTT, LSS, 0, scale);
    gemm_tf32<<<gP, 256>>>(attn, cross_wo, cross_bo, tmp,
                           cross_wo, cross_bo, tmp, cross_wo, cross_bo, tmp, MR, DD, DD, 0);
    add_ln<<<MR, 256>>>(x1, tmp, n2_g, n2_b, x2);

    // ---- feed-forward ----
    gemm_tf32<<<gFF1, 256>>>(x2, ff_w1, ff_b1, ff,
                             ff_w1, ff_b1, ff, ff_w1, ff_b1, ff, MR, DFFF, DD, 1);
    gemm_tf32<<<gP, 256>>>(ff, ff_w2, ff_b2, tmp,
                           ff_w2, ff_b2, tmp, ff_w2, ff_b2, tmp, MR, DD, DFFF, 0);
    add_ln<<<MR, 256>>>(x2, tmp, n3_g, n3_b, out);
}

// round 9
// speedup vs baseline: 2.9374x; 1.0820x over previous
#include <cuda_runtime.h>
#include <math.h>

// Problem dims
#define BB   2
#define LTT  2048
#define LSS  2048
#define DD   1024
#define HH   16
#define DKK  64
#define DFFF 4096
#define MR   (BB*LTT)   // 4096 rows
#define BH   (BB*HH)    // 32

// ---------------- scratch (__device__ globals, no allocs) ----------------
__device__ float g_q   [(size_t)MR*DD];
__device__ float g_k   [(size_t)MR*DD];
__device__ float g_v   [(size_t)MR*DD];
__device__ float g_attn[(size_t)MR*DD];
__device__ float g_tmp [(size_t)MR*DD];
__device__ float g_x1  [(size_t)MR*DD];
__device__ float g_x2  [(size_t)MR*DD];
__device__ float g_ff  [(size_t)MR*DFFF];

// ------------------------- tf32 helpers -----------------------------------
__device__ __forceinline__ unsigned f2tf32(float x) {
    unsigned y;
    asm("cvt.rna.tf32.f32 %0, %1;" : "=r"(y) : "f"(x));
    return y;
}
__device__ __forceinline__ unsigned raw2tf32(unsigned r) {
    return f2tf32(__uint_as_float(r));
}

// D += A(16x8) @ B(8x8), tf32 in, fp32 accum.  row.col layout.
__device__ __forceinline__ void mma8(float* d, const unsigned* a, const unsigned* b) {
    asm volatile(
        "mma.sync.aligned.m16n8k8.row.col.f32.tf32.tf32.f32 "
        "{%0,%1,%2,%3},{%4,%5,%6,%7},{%8,%9},{%0,%1,%2,%3};\n"
        : "+f"(d[0]), "+f"(d[1]), "+f"(d[2]), "+f"(d[3])
        : "r"(a[0]), "r"(a[1]), "r"(a[2]), "r"(a[3]), "r"(b[0]), "r"(b[1]));
}

// 16B async copy gmem -> smem
__device__ __forceinline__ void cpa16(unsigned* dst, const void* src) {
    unsigned d = (unsigned)__cvta_generic_to_shared(dst);
    asm volatile("cp.async.cg.shared.global [%0], [%1], 16;\n" :: "r"(d), "l"(src));
}

// ---------------- TF32 GEMM: C = A[M,K] @ W[K,N] + bias (+gelu) -----------
// 128x128 block tile, BK=32, 256 threads (8 warps, 2x4), warp tile 64x32.
// 2-stage cp.async double buffer; raw fp32 in smem, cvt.rna on fragment load.
// grid.z selects among up to 3 (W,bias,C) sets sharing the same A (fused QKV).
#define G_AS_WORDS   (128 * 36)
#define G_BS_WORDS   (32 * 136)
#define G_STAGE      (G_AS_WORDS + G_BS_WORDS)      // 8960 words
#define G_SMEM_BYTES (2 * G_STAGE * 4)              // 71680 B

__global__ void __launch_bounds__(256, 2) gemm_tf32(
    const float* __restrict__ A,
    const float* __restrict__ W0, const float* __restrict__ b0, float* __restrict__ C0,
    const float* __restrict__ W1, const float* __restrict__ b1, float* __restrict__ C1,
    const float* __restrict__ W2, const float* __restrict__ b2, float* __restrict__ C2,
    int M, int N, int K, int act)
{
    const float* W = W0; const float* bias = b0; float* C = C0;
    if (blockIdx.z == 1) { W = W1; bias = b1; C = C1; }
    else if (blockIdx.z == 2) { W = W2; bias = b2; C = C2; }

    extern __shared__ unsigned gsm[];

    const int tid  = threadIdx.x;
    const int brow = blockIdx.y << 7;
    const int bcol = blockIdx.x << 7;
    const int w    = tid >> 5, lane = tid & 31;
    const int wm   = (w & 1) << 6;
    const int wn   = (w >> 1) << 5;
    const int lr   = lane >> 2, lc = lane & 3;

    const int arow = tid >> 1;                 // 0..127
    const int acol = (tid & 1) << 4;           // 0 / 16
    const int brw  = tid >> 3;                 // 0..31
    const int bcl  = (tid & 7) << 4;           // 0..112

    const float* Abase = A + (size_t)(brow + arow) * K + acol;
    const float* Wbase = W + (size_t)brw * N + bcol + bcl;

    float acc[4][4][4];
    #pragma unroll
    for (int mt = 0; mt < 4; mt++)
        #pragma unroll
        for (int nt = 0; nt < 4; nt++)
            #pragma unroll
            for (int i = 0; i < 4; i++) acc[mt][nt][i] = 0.f;

    // ---- prologue: chunk 0 into stage 0 ----
    {
        unsigned* As = gsm;
        unsigned* Bs = gsm + G_AS_WORDS;
        #pragma unroll
        for (int i = 0; i < 4; i++)
            cpa16(&As[arow * 36 + acol + i * 4], Abase + i * 4);
        #pragma unroll
        for (int i = 0; i < 4; i++)
            cpa16(&Bs[brw * 136 + bcl + i * 4], Wbase + i * 4);
        asm volatile("cp.async.commit_group;\n");
    }

    for (int k0 = 0; k0 < K; k0 += 32) {
        const int cur = (k0 >> 5) & 1;
        if (k0 + 32 < K) {
            unsigned* As = gsm + (cur ^ 1) * G_STAGE;
            unsigned* Bs = As + G_AS_WORDS;
            const float* Ap = Abase + k0 + 32;
            const float* Wp = Wbase + (size_t)(k0 + 32) * N;
            #pragma unroll
            for (int i = 0; i < 4; i++)
                cpa16(&As[arow * 36 + acol + i * 4], Ap + i * 4);
            #pragma unroll
            for (int i = 0; i < 4; i++)
                cpa16(&Bs[brw * 136 + bcl + i * 4], Wp + i * 4);
            asm volatile("cp.async.commit_group;\n");
            asm volatile("cp.async.wait_group 1;\n");
        } else {
            asm volatile("cp.async.wait_group 0;\n");
        }
        __syncthreads();

        const unsigned* As = gsm + cur * G_STAGE;
        const unsigned* Bs = As + G_AS_WORDS;

        #pragma unroll
        for (int ks = 0; ks < 4; ks++) {
            unsigned a[4][4], bfr[4][2];
            #pragma unroll
            for (int mt = 0; mt < 4; mt++) {
                int r = wm + (mt << 4) + lr;
                int c = (ks << 3) + lc;
                a[mt][0] = raw2tf32(As[r * 36 + c]);
                a[mt][1] = raw2tf32(As[(r + 8) * 36 + c]);
                a[mt][2] = raw2tf32(As[r * 36 + c + 4]);
                a[mt][3] = raw2tf32(As[(r + 8) * 36 + c + 4]);
            }
            #pragma unroll
            for (int nt = 0; nt < 4; nt++) {
                int kk = (ks << 3) + lc;
                int c  = wn + (nt << 3) + lr;
                bfr[nt][0] = raw2tf32(Bs[kk * 136 + c]);
                bfr[nt][1] = raw2tf32(Bs[(kk + 4) * 136 + c]);
            }
            #pragma unroll
            for (int mt = 0; mt < 4; mt++)
                #pragma unroll
                for (int nt = 0; nt < 4; nt++)
                    mma8(acc[mt][nt], a[mt], bfr[nt]);
        }
        __syncthreads();
    }

    #pragma unroll
    for (int mt = 0; mt < 4; mt++) {
        #pragma unroll
        for (int nt = 0; nt < 4; nt++) {
            int r0 = brow + wm + (mt << 4) + lr;
            int c0 = bcol + wn + (nt << 3) + (lc << 1);
            float bx = bias[c0], by = bias[c0 + 1];
            float v0 = acc[mt][nt][0] + bx, v1 = acc[mt][nt][1] + by;
            float v2 = acc[mt][nt][2] + bx, v3 = acc[mt][nt][3] + by;
            if (act == 1) {
                v0 = 0.5f * v0 * (1.f + erff(v0 * 0.70710678f));
                v1 = 0.5f * v1 * (1.f + erff(v1 * 0.70710678f));
                v2 = 0.5f * v2 * (1.f + erff(v2 * 0.70710678f));
                v3 = 0.5f * v3 * (1.f + erff(v3 * 0.70710678f));
            }
            float2 lo = {v0, v1}, hi = {v2, v3};
            *(float2*)(C + (size_t)r0 * N + c0)       = lo;
            *(float2*)(C + (size_t)(r0 + 8) * N + c0) = hi;
        }
    }
}

// ---------------- fused flash attention ------------------------------------
// O = softmax(scale * Q @ K^T [+causal mask]) @ V, one kernel, no gmem S.
// Block: 128 threads (4 warps), Q tile = 64 rows, KV tile = 64 per iter.
// Warp w owns rows [w*16, w*16+16) -> online-softmax stats are warp-local
// (quad shuffles only). P staged through warp-private smem for the 2nd mma.
// smem words:  Qs [64][68] | Ks [64][68] | Vs [64][72] | Ps [64][68]
#define FA_SMEM_WORDS (4352 + 4352 + 4608 + 4352)
#define FA_SMEM_BYTES (FA_SMEM_WORDS * 4)

__global__ void __launch_bounds__(128) flash_attn(
    const float* __restrict__ Q, const float* __restrict__ Km,
    const float* __restrict__ V, float* __restrict__ O,
    int Lq, int Lk, int causal, float scale)
{
    extern __shared__ unsigned sm[];
    unsigned* Qs = sm;
    unsigned* Ks = sm + 4352;
    unsigned* Vs = sm + 8704;
    unsigned* Ps = sm + 13312;

    const int bh = blockIdx.y, b = bh >> 4, h = bh & 15;
    const int i0 = (gridDim.x - 1 - blockIdx.x) << 6;   // heavy tiles first
    const int tid = threadIdx.x;
    const int w = tid >> 5, lane = tid & 31;
    const int lr = lane >> 2, lc = lane & 3;

    // ---- load Q tile once, scale folded in ----
    for (int idx = tid; idx < 1024; idx += 128) {
        int r = idx >> 4, c = (idx & 15) << 2;
        float4 v = *(const float4*)(Q + (size_t)(b * Lq + i0 + r) * DD + h * DKK + c);
        unsigned* d = &Qs[r * 68 + c];
        d[0] = f2tf32(v.x * scale); d[1] = f2tf32(v.y * scale);
        d[2] = f2tf32(v.z * scale); d[3] = f2tf32(v.w * scale);
    }

    float o[8][4];
    #pragma unroll
    for (int nt = 0; nt < 8; nt++)
        #pragma unroll
        for (int i = 0; i < 4; i++) o[nt][i] = 0.f;
    float m0 = -1e30f, m1 = -1e30f, l0 = 0.f, l1 = 0.f;

    const int r = (w << 4) + lr;            // warp-local A-frag row
    const int jend = causal ? (i0 + 64) : Lk;

    for (int j0 = 0; j0 < jend; j0 += 64) {
        __syncthreads();                     // prev iter done before overwrite
        for (int idx = tid; idx < 1024; idx += 128) {
            int rr = idx >> 4, c = (idx & 15) << 2;
            float4 kv = *(const float4*)(Km + (size_t)(b * Lk + j0 + rr) * DD + h * DKK + c);
            unsigned* kd = &Ks[rr * 68 + c];
            kd[0] = f2tf32(kv.x); kd[1] = f2tf32(kv.y);
            kd[2] = f2tf32(kv.z); kd[3] = f2tf32(kv.w);
            float4 vv = *(const float4*)(V + (size_t)(b * Lk + j0 + rr) * DD + h * DKK + c);
            unsigned* vd = &Vs[rr * 72 + c];
            vd[0] = f2tf32(vv.x); vd[1] = f2tf32(vv.y);
            vd[2] = f2tf32(vv.z); vd[3] = f2tf32(vv.w);
        }
        __syncthreads();

        // ---- S = Qs @ Ks^T ----
        float s[8][4];
        #pragma unroll
        for (int nt = 0; nt < 8; nt++)
            #pragma unroll
            for (int i = 0; i < 4; i++) s[nt][i] = 0.f;

        #pragma unroll
        for (int ks = 0; ks < 8; ks++) {
            unsigned a[4];
            int c = (ks << 3) + lc;
            a[0] = Qs[r * 68 + c];
            a[1] = Qs[(r + 8) * 68 + c];
            a[2] = Qs[r * 68 + c + 4];
            a[3] = Qs[(r + 8) * 68 + c + 4];
            #pragma unroll
            for (int nt = 0; nt < 8; nt++) {
                unsigned bb[2];
                int n = (nt << 3) + lr;
                bb[0] = Ks[n * 68 + c];
                bb[1] = Ks[n * 68 + c + 4];
                mma8(s[nt], a, bb);
            }
        }

        // ---- causal mask (diagonal tile only) ----
        if (causal && j0 + 64 > i0) {
            int ig = i0 + r;
            #pragma unroll
            for (int nt = 0; nt < 8; nt++) {
                int jg = j0 + (nt << 3) + (lc << 1);
                if (jg     > ig)     s[nt][0] = -1e30f;
                if (jg + 1 > ig)     s[nt][1] = -1e30f;
                if (jg     > ig + 8) s[nt][2] = -1e30f;
                if (jg + 1 > ig + 8) s[nt][3] = -1e30f;
            }
        }

        // ---- online softmax (rows lr / lr+8 of this warp strip) ----
        float mx0 = -1e30f, mx1 = -1e30f;
        #pragma unroll
        for (int nt = 0; nt < 8; nt++) {
            mx0 = fmaxf(mx0, fmaxf(s[nt][0], s[nt][1]));
            mx1 = fmaxf(mx1, fmaxf(s[nt][2], s[nt][3]));
        }
        mx0 = fmaxf(mx0, __shfl_xor_sync(0xffffffffu, mx0, 1));
        mx0 = fmaxf(mx0, __shfl_xor_sync(0xffffffffu, mx0, 2));
        mx1 = fmaxf(mx1, __shfl_xor_sync(0xffffffffu, mx1, 1));
        mx1 = fmaxf(mx1, __shfl_xor_sync(0xffffffffu, mx1, 2));

        float mn0 = fmaxf(m0, mx0), mn1 = fmaxf(m1, mx1);
        float al0 = __expf(m0 - mn0), al1 = __expf(m1 - mn1);
        m0 = mn0; m1 = mn1;

        float sum0 = 0.f, sum1 = 0.f;
        #pragma unroll
        for (int nt = 0; nt < 8; nt++) {
            float p0 = __expf(s[nt][0] - mn0), p1 = __expf(s[nt][1] - mn0);
            float p2 = __expf(s[nt][2] - mn1), p3 = __expf(s[nt][3] - mn1);
            sum0 += p0 + p1; sum1 += p2 + p3;
            int c = (nt << 3) + (lc << 1);
            Ps[r * 68 + c]           = f2tf32(p0);
            Ps[r * 68 + c + 1]       = f2tf32(p1);
            Ps[(r + 8) * 68 + c]     = f2tf32(p2);
            Ps[(r + 8) * 68 + c + 1] = f2tf32(p3);
            o[nt][0] *= al0; o[nt][1] *= al0;
            o[nt][2] *= al1; o[nt][3] *= al1;
        }
        sum0 += __shfl_xor_sync(0xffffffffu, sum0, 1);
        sum0 += __shfl_xor_sync(0xffffffffu, sum0, 2);
        sum1 += __shfl_xor_sync(0xffffffffu, sum1, 1);
        sum1 += __shfl_xor_sync(0xffffffffu, sum1, 2);
        l0 = l0 * al0 + sum0;
        l1 = l1 * al1 + sum1;
        __syncwarp();                        // Ps visible within warp

        // ---- O += P @ V ----
        #pragma unroll
        for (int ks = 0; ks < 8; ks++) {
            unsigned a[4];
            int c = (ks << 3) + lc;          // shared k index
            a[0] = Ps[r * 68 + c];
            a[1] = Ps[(r + 8) * 68 + c];
            a[2] = Ps[r * 68 + c + 4];
            a[3] = Ps[(r + 8) * 68 + c + 4];
            #pragma unroll
            for (int nt = 0; nt < 8; nt++) {
                unsigned bb[2];
                int n = (nt << 3) + lr;
                bb[0] = Vs[c * 72 + n];
                bb[1] = Vs[(c + 4) * 72 + n];
                mma8(o[nt], a, bb);
            }
        }
    }

    // ---- normalize + store ----
    const float inv0 = 1.f / l0, inv1 = 1.f / l1;
    const int ig = b * Lq + i0 + r;
    #pragma unroll
    for (int nt = 0; nt < 8; nt++) {
        int c = h * DKK + (nt << 3) + (lc << 1);
        float2 lo = {o[nt][0] * inv0, o[nt][1] * inv0};
        float2 hi = {o[nt][2] * inv1, o[nt][3] * inv1};
        *(float2*)(O + (size_t)ig * DD + c)       = lo;
        *(float2*)(O + (size_t)(ig + 8) * DD + c) = hi;
    }
}

// -------------------- out = LayerNorm(a + r) * g + beta ------------------
__global__ void __launch_bounds__(256) add_ln(
    const float* __restrict__ a, const float* __restrict__ r,
    const float* __restrict__ g, const float* __restrict__ beta,
    float* __restrict__ out)
{
    __shared__ float rs[256], rss[256];
    const size_t row = blockIdx.x;
    const int tid = threadIdx.x;
    const int c = tid << 2;
    float4 av = *(const float4*)(a + row * DD + c);
    float4 rv = *(const float4*)(r + row * DD + c);
    float x0 = av.x + rv.x, x1 = av.y + rv.y, x2 = av.z + rv.z, x3 = av.w + rv.w;
    rs[tid]  = x0 + x1 + x2 + x3;
    rss[tid] = x0 * x0 + x1 * x1 + x2 * x2 + x3 * x3;
    __syncthreads();
    for (int s = 128; s > 0; s >>= 1) {
        if (tid < s) { rs[tid] += rs[tid + s]; rss[tid] += rss[tid + s]; }
        __syncthreads();
    }
    const float mu  = rs[0] * (1.f / DD);
    const float var = rss[0] * (1.f / DD) - mu * mu;
    const float inv = rsqrtf(var + 1e-5f);
    float4 gv = *(const float4*)(g + c);
    float4 bv = *(const float4*)(beta + c);
    float4 o;
    o.x = (x0 - mu) * inv * gv.x + bv.x;
    o.y = (x1 - mu) * inv * gv.y + bv.y;
    o.z = (x2 - mu) * inv * gv.z + bv.z;
    o.w = (x3 - mu) * inv * gv.w + bv.w;
    *(float4*)(out + row * DD + c) = o;
}

// ---------------------------------------------------------------------------
extern "C" void kernel_launch(void* const* d_in, const int* in_sizes, int n_in,
                              void* d_out, int out_size)
{
    const float* x        = (const float*)d_in[0];
    const float* enc      = (const float*)d_in[1];
    const float* self_wq = (const float*)d_in[4],  *self_bq = (const float*)d_in[5];
    const float* self_wk = (const float*)d_in[6],  *self_bk = (const float*)d_in[7];
    const float* self_wv = (const float*)d_in[8],  *self_bv = (const float*)d_in[9];
    const float* self_wo = (const float*)d_in[10], *self_bo = (const float*)d_in[11];
    const float* cross_wq = (const float*)d_in[12], *cross_bq = (const float*)d_in[13];
    const float* cross_wk = (const float*)d_in[14], *cross_bk = (const float*)d_in[15];
    const float* cross_wv = (const float*)d_in[16], *cross_bv = (const float*)d_in[17];
    const float* cross_wo = (const float*)d_in[18], *cross_bo = (const float*)d_in[19];
    const float* ff_w1 = (const float*)d_in[20], *ff_b1 = (const float*)d_in[21];
    const float* ff_w2 = (const float*)d_in[22], *ff_b2 = (const float*)d_in[23];
    const float* n1_g = (const float*)d_in[24], *n1_b = (const float*)d_in[25];
    const float* n2_g = (const float*)d_in[26], *n2_b = (const float*)d_in[27];
    const float* n3_g = (const float*)d_in[28], *n3_b = (const float*)d_in[29];
    float* out = (float*)d_out;

    float *q, *k, *v, *attn, *tmp, *x1, *x2, *ff;
    cudaGetSymbolAddress((void**)&q,    g_q);
    cudaGetSymbolAddress((void**)&k,    g_k);
    cudaGetSymbolAddress((void**)&v,    g_v);
    cudaGetSymbolAddress((void**)&attn, g_attn);
    cudaGetSymbolAddress((void**)&tmp,  g_tmp);
    cudaGetSymbolAddress((void**)&x1,   g_x1);
    cudaGetSymbolAddress((void**)&x2,   g_x2);
    cudaGetSymbolAddress((void**)&ff,   g_ff);

    cudaFuncSetAttribute(flash_attn,
                         cudaFuncAttributeMaxDynamicSharedMemorySize, FA_SMEM_BYTES);
    cudaFuncSetAttribute(gemm_tf32,
                         cudaFuncAttributeMaxDynamicSharedMemorySize, G_SMEM_BYTES);

    const dim3 gQKV(DD / 128, MR / 128, 3);
    const dim3 gKV (DD / 128, MR / 128, 2);
    const dim3 gP  (DD / 128, MR / 128, 1);
    const dim3 gFF1(DFFF / 128, MR / 128, 1);
    const dim3 gFA (LTT / 64, BH);
    const float scale = 0.125f;              // 1/sqrt(64)

    // ---- self-attention (causal) ----
    gemm_tf32<<<gQKV, 256, G_SMEM_BYTES>>>(x, self_wq, self_bq, q, self_wk, self_bk, k,
                             self_wv, self_bv, v, MR, DD, DD, 0);
    flash_attn<<<gFA, 128, FA_SMEM_BYTES>>>(q, k, v, attn, LTT, LTT, 1, scale);
    gemm_tf32<<<gP, 256, G_SMEM_BYTES>>>(attn, self_wo, self_bo, tmp,
                           self_wo, self_bo, tmp, self_wo, self_bo, tmp, MR, DD, DD, 0);
    add_ln<<<MR, 256>>>(x, tmp, n1_g, n1_b, x1);

    // ---- cross-attention (no mask) ----
    gemm_tf32<<<gP, 256, G_SMEM_BYTES>>>(x1, cross_wq, cross_bq, q,
                           cross_wq, cross_bq, q, cross_wq, cross_bq, q, MR, DD, DD, 0);
    gemm_tf32<<<gKV, 256, G_SMEM_BYTES>>>(enc, cross_wk, cross_bk, k, cross_wv, cross_bv, v,
                            cross_wv, cross_bv, v, MR, DD, DD, 0);
    flash_attn<<<gFA, 128, FA_SMEM_BYTES>>>(q, k, v, attn, LTT, LSS, 0, scale);
    gemm_tf32<<<gP, 256, G_SMEM_BYTES>>>(attn, cross_wo, cross_bo, tmp,
                           cross_wo, cross_bo, tmp, cross_wo, cross_bo, tmp, MR, DD, DD, 0);
    add_ln<<<MR, 256>>>(x1, tmp, n2_g, n2_b, x2);

    // ---- feed-forward ----
    gemm_tf32<<<gFF1, 256, G_SMEM_BYTES>>>(x2, ff_w1, ff_b1, ff,
                             ff_w1, ff_b1, ff, ff_w1, ff_b1, ff, MR, DFFF, DD, 1);
    gemm_tf32<<<gP, 256, G_SMEM_BYTES>>>(ff, ff_w2, ff_b2, tmp,
                           ff_w2, ff_b2, tmp, ff_w2, ff_b2, tmp, MR, DD, DFFF, 0);
    add_ln<<<MR, 256>>>(x2, tmp, n3_g, n3_b, out);
}